// round 9
// baseline (speedup 1.0000x reference)
#include <cuda_runtime.h>
#include <cstdint>
#include <cstddef>

#define EPSV 1e-5f

// ---------------- scratch (static device globals; no allocation) ----------------
// stage1 output rows: rgb 256*49, depth 256*49, mmwave 256*32, lidar 256*32 = 41472 rows x 512
__device__ float g_H[41472 * 512];
__device__ float g_h1[32768 * 128];      // posenc layer-1 activations [b*128+s][c]
__device__ float g_newxyz[256 * 128 * 3];

// ---------------- threefry2x32 (JAX partitionable path) ----------------
__device__ __forceinline__ void tf_round(uint32_t& v0, uint32_t& v1, int r) {
    v0 += v1;
    v1 = (v1 << r) | (v1 >> (32 - r));
    v1 ^= v0;
}

__device__ __forceinline__ void threefry2x32(uint32_t k0, uint32_t k1,
                                             uint32_t x0, uint32_t x1,
                                             uint32_t& o0, uint32_t& o1) {
    uint32_t ks0 = k0, ks1 = k1, ks2 = k0 ^ k1 ^ 0x1BD11BDAu;
    uint32_t v0 = x0 + ks0, v1 = x1 + ks1;
    tf_round(v0, v1, 13); tf_round(v0, v1, 15); tf_round(v0, v1, 26); tf_round(v0, v1, 6);
    v0 += ks1; v1 += ks2 + 1u;
    tf_round(v0, v1, 17); tf_round(v0, v1, 29); tf_round(v0, v1, 16); tf_round(v0, v1, 24);
    v0 += ks2; v1 += ks0 + 2u;
    tf_round(v0, v1, 13); tf_round(v0, v1, 15); tf_round(v0, v1, 26); tf_round(v0, v1, 6);
    v0 += ks0; v1 += ks1 + 3u;
    tf_round(v0, v1, 17); tf_round(v0, v1, 29); tf_round(v0, v1, 16); tf_round(v0, v1, 24);
    v0 += ks1; v1 += ks2 + 4u;
    tf_round(v0, v1, 13); tf_round(v0, v1, 15); tf_round(v0, v1, 26); tf_round(v0, v1, 6);
    v0 += ks2; v1 += ks0 + 5u;
    o0 = v0; o1 = v1;
}

// jax.random.randint(key(42), (256,), 0, 4096):
//   span = 4096 -> multiplier = (2^16 % 4096)^2 % 4096 = 0 -> result = lower_bits % 4096
//   lower_bits from second subkey of fold-like split; partitionable 32-bit draw = out0 ^ out1
__device__ __forceinline__ int fps_seed_index(int b) {
    uint32_t ka, kb, ra, rb;
    threefry2x32(0u, 42u, 0u, 1u, ka, kb);                 // subkey #2 of split(key(42))
    threefry2x32(ka, kb, 0u, (uint32_t)b, ra, rb);         // counts = (hi=0, lo=b)
    return (int)((ra ^ rb) & 4095u);
}

// ---------------- K1: farthest point sampling (points in registers, tiny smem) --------
__global__ void __launch_bounds__(256) fps_kernel(const float* __restrict__ pts) {
    __shared__ float rv[8];
    __shared__ int   ri[8];
    __shared__ float sc[3];
    __shared__ int   sFar;

    const int b = blockIdx.x;
    const int t = threadIdx.x;
    const float* P = pts + (size_t)b * 4096 * 3;

    float px[16], py[16], pz[16], dist[16];
#pragma unroll
    for (int k = 0; k < 16; k++) {
        int j = t + k * 256;
        px[k] = P[j * 3 + 0];
        py[k] = P[j * 3 + 1];
        pz[k] = P[j * 3 + 2];
        dist[k] = 1e10f;
    }
    if (t == 0) sFar = fps_seed_index(b);
    __syncthreads();

    // broadcast initial centroid from its owner thread
    {
        int far = sFar;
#pragma unroll
        for (int k = 0; k < 16; k++)
            if (t + k * 256 == far) { sc[0] = px[k]; sc[1] = py[k]; sc[2] = pz[k]; }
    }
    __syncthreads();

    for (int it = 0; it < 128; it++) {
        float cx = sc[0], cy = sc[1], cz = sc[2];
        if (t == 0) {
            float* o = g_newxyz + ((size_t)b * 128 + it) * 3;
            o[0] = cx; o[1] = cy; o[2] = cz;
        }
        float best = -1.0f;
        int bi = 0x7fffffff;
#pragma unroll
        for (int k = 0; k < 16; k++) {
            int j = t + k * 256;
            float dx = px[k] - cx, dy = py[k] - cy, dz = pz[k] - cz;
            float d = dx * dx + dy * dy + dz * dz;
            float nd = fminf(dist[k], d);
            dist[k] = nd;
            if (nd > best) { best = nd; bi = j; }   // j increasing -> first occurrence kept
        }
        // warp argmax (lexicographic: larger val, then smaller index)
#pragma unroll
        for (int off = 16; off; off >>= 1) {
            float ov = __shfl_down_sync(0xffffffffu, best, off);
            int   oi = __shfl_down_sync(0xffffffffu, bi, off);
            if (ov > best || (ov == best && oi < bi)) { best = ov; bi = oi; }
        }
        if ((t & 31) == 0) { rv[t >> 5] = best; ri[t >> 5] = bi; }
        __syncthreads();
        if (t < 32) {
            float v = (t < 8) ? rv[t] : -1e30f;
            int   ix = (t < 8) ? ri[t] : 0x7fffffff;
#pragma unroll
            for (int off = 4; off; off >>= 1) {
                float ov = __shfl_down_sync(0xffffffffu, v, off);
                int   oi = __shfl_down_sync(0xffffffffu, ix, off);
                if (ov > v || (ov == v && oi < ix)) { v = ov; ix = oi; }
            }
            if (t == 0) sFar = ix;
        }
        __syncthreads();
        {
            int far = sFar;
#pragma unroll
            for (int k = 0; k < 16; k++)
                if (t + k * 256 == far) { sc[0] = px[k]; sc[1] = py[k]; sc[2] = pz[k]; }
        }
        __syncthreads();
    }
}

// ---------------- K2: conv1d(k=1) GEMM + BN + ReLU (K=512) ----------------
#define BKK 16
#define LDT 132

__global__ void __launch_bounds__(256, 2) gemm_bn_relu_kernel(
    const float* __restrict__ X,     // [M, 512], K contiguous
    const float* __restrict__ W,     // [512, 512], row o, K contiguous
    const float* __restrict__ cb,
    const float* __restrict__ gg,
    const float* __restrict__ bbeta,
    const float* __restrict__ bmean,
    const float* __restrict__ bvar,
    int regionStart)
{
    __shared__ float As[BKK * LDT];
    __shared__ float Bs[BKK * LDT];

    const int t = threadIdx.x;
    const int row0 = blockIdx.x * 128;
    const int col0 = blockIdx.y * 128;
    const int ar0 = t >> 2;     // 0..63
    const int aq  = t & 3;      // which float4 in the 16-float K-slab

    const float* Ag0 = X + (size_t)(row0 + ar0) * 512 + aq * 4;
    const float* Ag1 = Ag0 + (size_t)64 * 512;
    const float* Bg0 = W + (size_t)(col0 + ar0) * 512 + aq * 4;
    const float* Bg1 = Bg0 + (size_t)64 * 512;

    const int tx = t & 15, ty = t >> 4;

    float acc[8][8];
#pragma unroll
    for (int i = 0; i < 8; i++)
#pragma unroll
        for (int j = 0; j < 8; j++) acc[i][j] = 0.0f;

    {
        float4 a0 = *(const float4*)Ag0;
        float4 a1 = *(const float4*)Ag1;
        float4 b0 = *(const float4*)Bg0;
        float4 b1 = *(const float4*)Bg1;
        int kb = aq * 4;
        As[(kb + 0) * LDT + ar0] = a0.x; As[(kb + 1) * LDT + ar0] = a0.y;
        As[(kb + 2) * LDT + ar0] = a0.z; As[(kb + 3) * LDT + ar0] = a0.w;
        As[(kb + 0) * LDT + ar0 + 64] = a1.x; As[(kb + 1) * LDT + ar0 + 64] = a1.y;
        As[(kb + 2) * LDT + ar0 + 64] = a1.z; As[(kb + 3) * LDT + ar0 + 64] = a1.w;
        Bs[(kb + 0) * LDT + ar0] = b0.x; Bs[(kb + 1) * LDT + ar0] = b0.y;
        Bs[(kb + 2) * LDT + ar0] = b0.z; Bs[(kb + 3) * LDT + ar0] = b0.w;
        Bs[(kb + 0) * LDT + ar0 + 64] = b1.x; Bs[(kb + 1) * LDT + ar0 + 64] = b1.y;
        Bs[(kb + 2) * LDT + ar0 + 64] = b1.z; Bs[(kb + 3) * LDT + ar0 + 64] = b1.w;
    }
    __syncthreads();

    for (int tt = 0; tt < 32; tt++) {
        float4 a0, a1, b0, b1;
        const bool more = (tt + 1) < 32;
        if (more) {
            int kk = (tt + 1) * BKK;
            a0 = *(const float4*)(Ag0 + kk);
            a1 = *(const float4*)(Ag1 + kk);
            b0 = *(const float4*)(Bg0 + kk);
            b1 = *(const float4*)(Bg1 + kk);
        }
#pragma unroll
        for (int k = 0; k < BKK; k++) {
            float a[8], bv[8];
            *(float4*)&a[0]  = *(const float4*)&As[k * LDT + ty * 8];
            *(float4*)&a[4]  = *(const float4*)&As[k * LDT + ty * 8 + 4];
            *(float4*)&bv[0] = *(const float4*)&Bs[k * LDT + tx * 8];
            *(float4*)&bv[4] = *(const float4*)&Bs[k * LDT + tx * 8 + 4];
#pragma unroll
            for (int i = 0; i < 8; i++)
#pragma unroll
                for (int j = 0; j < 8; j++)
                    acc[i][j] = fmaf(a[i], bv[j], acc[i][j]);
        }
        __syncthreads();
        if (more) {
            int kb = aq * 4;
            As[(kb + 0) * LDT + ar0] = a0.x; As[(kb + 1) * LDT + ar0] = a0.y;
            As[(kb + 2) * LDT + ar0] = a0.z; As[(kb + 3) * LDT + ar0] = a0.w;
            As[(kb + 0) * LDT + ar0 + 64] = a1.x; As[(kb + 1) * LDT + ar0 + 64] = a1.y;
            As[(kb + 2) * LDT + ar0 + 64] = a1.z; As[(kb + 3) * LDT + ar0 + 64] = a1.w;
            Bs[(kb + 0) * LDT + ar0] = b0.x; Bs[(kb + 1) * LDT + ar0] = b0.y;
            Bs[(kb + 2) * LDT + ar0] = b0.z; Bs[(kb + 3) * LDT + ar0] = b0.w;
            Bs[(kb + 0) * LDT + ar0 + 64] = b1.x; Bs[(kb + 1) * LDT + ar0 + 64] = b1.y;
            Bs[(kb + 2) * LDT + ar0 + 64] = b1.z; Bs[(kb + 3) * LDT + ar0 + 64] = b1.w;
            __syncthreads();
        }
    }

    // fused BN + ReLU epilogue: val = relu((acc + cb - mean)*alpha + beta_bn)
    float alpha[8], beta[8];
#pragma unroll
    for (int j = 0; j < 8; j++) {
        int o = col0 + tx * 8 + j;
        float al = gg[o] * rsqrtf(bvar[o] + EPSV);
        alpha[j] = al;
        beta[j] = (cb[o] - bmean[o]) * al + bbeta[o];
    }
    float* Hbase = g_H + (size_t)regionStart * 512;
#pragma unroll
    for (int i = 0; i < 8; i++) {
        float ov[8];
#pragma unroll
        for (int j = 0; j < 8; j++)
            ov[j] = fmaxf(fmaf(acc[i][j], alpha[j], beta[j]), 0.0f);
        float* hp = Hbase + (size_t)(row0 + ty * 8 + i) * 512 + col0 + tx * 8;
        *(float4*)hp       = make_float4(ov[0], ov[1], ov[2], ov[3]);
        *(float4*)(hp + 4) = make_float4(ov[4], ov[5], ov[6], ov[7]);
    }
}

// ---------------- K3: token linear (L -> 32) + ReLU, writes proj into d_out ----------------
__global__ void __launch_bounds__(256) stage2_kernel(
    const float* __restrict__ lwimg, const float* __restrict__ lbimg,
    const float* __restrict__ lwpc,  const float* __restrict__ lbpc,
    float* __restrict__ out)
{
    const int b = blockIdx.x, m = blockIdx.y, t = threadIdx.x;
    const int L = (m < 2) ? 49 : 32;
    const int start = (m < 2) ? m * 12544 : 25088 + (m - 2) * 8192;
    const float* lw = (m == 0) ? lwimg
                    : (m == 1) ? lwimg + 32 * 49
                    : (m == 2) ? lwpc
                               : lwpc + 32 * 32;
    const float* lb = (m < 2) ? lbimg + m * 32 : lbpc + (m - 2) * 32;

    __shared__ float slw[32 * 49];
    for (int i = t; i < 32 * L; i += 256) slw[i] = lw[i];
    __syncthreads();

    const int o0 = (t & 63) * 8;
    const int s0 = (t >> 6) * 8;
    float acc[8][8];
#pragma unroll
    for (int i = 0; i < 8; i++)
#pragma unroll
        for (int j = 0; j < 8; j++) acc[i][j] = 0.0f;

    const float* hp = g_H + (size_t)(start + b * L) * 512 + o0;
    for (int l = 0; l < L; l++) {
        float4 h0 = *(const float4*)hp;
        float4 h1 = *(const float4*)(hp + 4);
        hp += 512;
        float hv[8] = {h0.x, h0.y, h0.z, h0.w, h1.x, h1.y, h1.z, h1.w};
#pragma unroll
        for (int i = 0; i < 8; i++) {
            float w = slw[(s0 + i) * L + l];
#pragma unroll
            for (int j = 0; j < 8; j++) acc[i][j] = fmaf(w, hv[j], acc[i][j]);
        }
    }
#pragma unroll
    for (int i = 0; i < 8; i++) {
        int s = s0 + i;
        float bias = lb[s];
        float ov[8];
#pragma unroll
        for (int j = 0; j < 8; j++) ov[j] = fmaxf(acc[i][j] + bias, 0.0f);
        float* op = out + ((size_t)b * 128 + m * 32 + s) * 512 + o0;
        *(float4*)op       = make_float4(ov[0], ov[1], ov[2], ov[3]);
        *(float4*)(op + 4) = make_float4(ov[4], ov[5], ov[6], ov[7]);
    }
}

// ---------------- K4a: posenc layer 1 (3 -> 128) + BN + ReLU, elementwise ----------------
__global__ void __launch_bounds__(256) h1_kernel(
    const float* __restrict__ w1, const float* __restrict__ b1,
    const float* __restrict__ g1, const float* __restrict__ bb1,
    const float* __restrict__ m1, const float* __restrict__ v1)
{
    int idx = blockIdx.x * 256 + threadIdx.x;     // over 32768*128
    int row = idx >> 7;                           // b*128 + s
    int c = idx & 127;
    const float* xyz = g_newxyz + (size_t)row * 3;
    float x = xyz[0], y = xyz[1], z = xyz[2];
    float v = w1[c * 3 + 0] * x + w1[c * 3 + 1] * y + w1[c * 3 + 2] * z + b1[c];
    float al = g1[c] * rsqrtf(v1[c] + EPSV);
    v = (v - m1[c]) * al + bb1[c];
    g_h1[(size_t)row * 128 + c] = fmaxf(v, 0.0f);
}

// ---------------- K4b: posenc layer 2 GEMM (M=32768, N=512, K=128) + BN + ReLU, += out --
__global__ void __launch_bounds__(256, 2) gemm_acc_kernel(
    const float* __restrict__ W,     // pe_w2 [512, 128], K contiguous
    const float* __restrict__ cb,    // pe_b2
    const float* __restrict__ gg,
    const float* __restrict__ bbeta,
    const float* __restrict__ bmean,
    const float* __restrict__ bvar,
    float* __restrict__ out)
{
    __shared__ float As[BKK * LDT];
    __shared__ float Bs[BKK * LDT];

    const int t = threadIdx.x;
    const int row0 = blockIdx.x * 128;
    const int col0 = blockIdx.y * 128;
    const int ar0 = t >> 2;
    const int aq  = t & 3;

    const float* Ag0 = g_h1 + (size_t)(row0 + ar0) * 128 + aq * 4;
    const float* Ag1 = Ag0 + (size_t)64 * 128;
    const float* Bg0 = W + (size_t)(col0 + ar0) * 128 + aq * 4;
    const float* Bg1 = Bg0 + (size_t)64 * 128;

    const int tx = t & 15, ty = t >> 4;

    float acc[8][8];
#pragma unroll
    for (int i = 0; i < 8; i++)
#pragma unroll
        for (int j = 0; j < 8; j++) acc[i][j] = 0.0f;

    {
        float4 a0 = *(const float4*)Ag0;
        float4 a1 = *(const float4*)Ag1;
        float4 b0 = *(const float4*)Bg0;
        float4 b1 = *(const float4*)Bg1;
        int kb = aq * 4;
        As[(kb + 0) * LDT + ar0] = a0.x; As[(kb + 1) * LDT + ar0] = a0.y;
        As[(kb + 2) * LDT + ar0] = a0.z; As[(kb + 3) * LDT + ar0] = a0.w;
        As[(kb + 0) * LDT + ar0 + 64] = a1.x; As[(kb + 1) * LDT + ar0 + 64] = a1.y;
        As[(kb + 2) * LDT + ar0 + 64] = a1.z; As[(kb + 3) * LDT + ar0 + 64] = a1.w;
        Bs[(kb + 0) * LDT + ar0] = b0.x; Bs[(kb + 1) * LDT + ar0] = b0.y;
        Bs[(kb + 2) * LDT + ar0] = b0.z; Bs[(kb + 3) * LDT + ar0] = b0.w;
        Bs[(kb + 0) * LDT + ar0 + 64] = b1.x; Bs[(kb + 1) * LDT + ar0 + 64] = b1.y;
        Bs[(kb + 2) * LDT + ar0 + 64] = b1.z; Bs[(kb + 3) * LDT + ar0 + 64] = b1.w;
    }
    __syncthreads();

    for (int tt = 0; tt < 8; tt++) {
        float4 a0, a1, b0, b1;
        const bool more = (tt + 1) < 8;
        if (more) {
            int kk = (tt + 1) * BKK;
            a0 = *(const float4*)(Ag0 + kk);
            a1 = *(const float4*)(Ag1 + kk);
            b0 = *(const float4*)(Bg0 + kk);
            b1 = *(const float4*)(Bg1 + kk);
        }
#pragma unroll
        for (int k = 0; k < BKK; k++) {
            float a[8], bv[8];
            *(float4*)&a[0]  = *(const float4*)&As[k * LDT + ty * 8];
            *(float4*)&a[4]  = *(const float4*)&As[k * LDT + ty * 8 + 4];
            *(float4*)&bv[0] = *(const float4*)&Bs[k * LDT + tx * 8];
            *(float4*)&bv[4] = *(const float4*)&Bs[k * LDT + tx * 8 + 4];
#pragma unroll
            for (int i = 0; i < 8; i++)
#pragma unroll
                for (int j = 0; j < 8; j++)
                    acc[i][j] = fmaf(a[i], bv[j], acc[i][j]);
        }
        __syncthreads();
        if (more) {
            int kb = aq * 4;
            As[(kb + 0) * LDT + ar0] = a0.x; As[(kb + 1) * LDT + ar0] = a0.y;
            As[(kb + 2) * LDT + ar0] = a0.z; As[(kb + 3) * LDT + ar0] = a0.w;
            As[(kb + 0) * LDT + ar0 + 64] = a1.x; As[(kb + 1) * LDT + ar0 + 64] = a1.y;
            As[(kb + 2) * LDT + ar0 + 64] = a1.z; As[(kb + 3) * LDT + ar0 + 64] = a1.w;
            Bs[(kb + 0) * LDT + ar0] = b0.x; Bs[(kb + 1) * LDT + ar0] = b0.y;
            Bs[(kb + 2) * LDT + ar0] = b0.z; Bs[(kb + 3) * LDT + ar0] = b0.w;
            Bs[(kb + 0) * LDT + ar0 + 64] = b1.x; Bs[(kb + 1) * LDT + ar0 + 64] = b1.y;
            Bs[(kb + 2) * LDT + ar0 + 64] = b1.z; Bs[(kb + 3) * LDT + ar0 + 64] = b1.w;
            __syncthreads();
        }
    }

    float alpha[8], beta[8];
#pragma unroll
    for (int j = 0; j < 8; j++) {
        int o = col0 + tx * 8 + j;
        float al = gg[o] * rsqrtf(bvar[o] + EPSV);
        alpha[j] = al;
        beta[j] = (cb[o] - bmean[o]) * al + bbeta[o];
    }
#pragma unroll
    for (int i = 0; i < 8; i++) {
        float* op = out + (size_t)(row0 + ty * 8 + i) * 512 + col0 + tx * 8;
        float4 c0 = *(float4*)op;
        float4 c1 = *(float4*)(op + 4);
        c0.x += fmaxf(fmaf(acc[i][0], alpha[0], beta[0]), 0.0f);
        c0.y += fmaxf(fmaf(acc[i][1], alpha[1], beta[1]), 0.0f);
        c0.z += fmaxf(fmaf(acc[i][2], alpha[2], beta[2]), 0.0f);
        c0.w += fmaxf(fmaf(acc[i][3], alpha[3], beta[3]), 0.0f);
        c1.x += fmaxf(fmaf(acc[i][4], alpha[4], beta[4]), 0.0f);
        c1.y += fmaxf(fmaf(acc[i][5], alpha[5], beta[5]), 0.0f);
        c1.z += fmaxf(fmaf(acc[i][6], alpha[6], beta[6]), 0.0f);
        c1.w += fmaxf(fmaf(acc[i][7], alpha[7], beta[7]), 0.0f);
        *(float4*)op       = c0;
        *(float4*)(op + 4) = c1;
    }
}

// ---------------- launch ----------------
extern "C" void kernel_launch(void* const* d_in, const int* in_sizes, int n_in,
                              void* d_out, int out_size) {
    const float* rgb     = (const float*)d_in[0];
    const float* depth   = (const float*)d_in[1];
    const float* mmwave  = (const float*)d_in[2];
    const float* lidar   = (const float*)d_in[3];
    const float* pts     = (const float*)d_in[4];
    const float* conv_w  = (const float*)d_in[5];
    const float* conv_b  = (const float*)d_in[6];
    const float* bn_g    = (const float*)d_in[7];
    const float* bn_b    = (const float*)d_in[8];
    const float* bn_m    = (const float*)d_in[9];
    const float* bn_v    = (const float*)d_in[10];
    const float* lwimg   = (const float*)d_in[11];
    const float* lbimg   = (const float*)d_in[12];
    const float* lwpc    = (const float*)d_in[13];
    const float* lbpc    = (const float*)d_in[14];
    const float* pw1     = (const float*)d_in[15];
    const float* pb1     = (const float*)d_in[16];
    const float* pg1     = (const float*)d_in[17];
    const float* pbb1    = (const float*)d_in[18];
    const float* pm1     = (const float*)d_in[19];
    const float* pv1     = (const float*)d_in[20];
    const float* pw2     = (const float*)d_in[21];
    const float* pb2     = (const float*)d_in[22];
    const float* pg2     = (const float*)d_in[23];
    const float* pbb2    = (const float*)d_in[24];
    const float* pm2     = (const float*)d_in[25];
    const float* pv2     = (const float*)d_in[26];
    float* out = (float*)d_out;

    // FPS (independent of GEMMs) — no dynamic smem
    fps_kernel<<<256, 256>>>(pts);

    // stage-1 GEMMs: region starts 0 / 12544 / 25088 / 33280
    gemm_bn_relu_kernel<<<dim3(98, 4), 256>>>(rgb,
        conv_w + 0 * 262144, conv_b + 0 * 512, bn_g + 0 * 512, bn_b + 0 * 512,
        bn_m + 0 * 512, bn_v + 0 * 512, 0);
    gemm_bn_relu_kernel<<<dim3(98, 4), 256>>>(depth,
        conv_w + 1 * 262144, conv_b + 1 * 512, bn_g + 1 * 512, bn_b + 1 * 512,
        bn_m + 1 * 512, bn_v + 1 * 512, 12544);
    gemm_bn_relu_kernel<<<dim3(64, 4), 256>>>(mmwave,
        conv_w + 2 * 262144, conv_b + 2 * 512, bn_g + 2 * 512, bn_b + 2 * 512,
        bn_m + 2 * 512, bn_v + 2 * 512, 25088);
    gemm_bn_relu_kernel<<<dim3(64, 4), 256>>>(lidar,
        conv_w + 3 * 262144, conv_b + 3 * 512, bn_g + 3 * 512, bn_b + 3 * 512,
        bn_m + 3 * 512, bn_v + 3 * 512, 33280);

    // stage-2: proj written to d_out
    stage2_kernel<<<dim3(256, 4), 256>>>(lwimg, lbimg, lwpc, lbpc, out);

    // posenc layer 1 (elementwise) then layer-2 GEMM accumulated into d_out
    h1_kernel<<<16384, 256>>>(pw1, pb1, pg1, pbb1, pm1, pv1);
    gemm_acc_kernel<<<dim3(256, 4), 256>>>(pw2, pb2, pg2, pbb2, pm2, pv2, out);
}

// round 10
// speedup vs baseline: 1.1451x; 1.1451x over previous
#include <cuda_runtime.h>
#include <mma.h>
#include <cstdint>
#include <cstddef>

using namespace nvcuda;

#define EPSV 1e-5f
#define LDA 36          // smem leading dim for 128x32 tiles (36*4B mult of 16B)
#define LDS_STG 20      // staging tile leading dim

// ---------------- scratch (static device globals; no allocation) ----------------
__device__ float g_H[41472 * 512];
__device__ float g_h1[32768 * 128];
__device__ float g_newxyz[256 * 128 * 3];

// ---------------- threefry2x32 (JAX partitionable path) ----------------
__device__ __forceinline__ void tf_round(uint32_t& v0, uint32_t& v1, int r) {
    v0 += v1;
    v1 = (v1 << r) | (v1 >> (32 - r));
    v1 ^= v0;
}

__device__ __forceinline__ void threefry2x32(uint32_t k0, uint32_t k1,
                                             uint32_t x0, uint32_t x1,
                                             uint32_t& o0, uint32_t& o1) {
    uint32_t ks0 = k0, ks1 = k1, ks2 = k0 ^ k1 ^ 0x1BD11BDAu;
    uint32_t v0 = x0 + ks0, v1 = x1 + ks1;
    tf_round(v0, v1, 13); tf_round(v0, v1, 15); tf_round(v0, v1, 26); tf_round(v0, v1, 6);
    v0 += ks1; v1 += ks2 + 1u;
    tf_round(v0, v1, 17); tf_round(v0, v1, 29); tf_round(v0, v1, 16); tf_round(v0, v1, 24);
    v0 += ks2; v1 += ks0 + 2u;
    tf_round(v0, v1, 13); tf_round(v0, v1, 15); tf_round(v0, v1, 26); tf_round(v0, v1, 6);
    v0 += ks0; v1 += ks1 + 3u;
    tf_round(v0, v1, 17); tf_round(v0, v1, 29); tf_round(v0, v1, 16); tf_round(v0, v1, 24);
    v0 += ks1; v1 += ks2 + 4u;
    tf_round(v0, v1, 13); tf_round(v0, v1, 15); tf_round(v0, v1, 26); tf_round(v0, v1, 6);
    v0 += ks2; v1 += ks0 + 5u;
    o0 = v0; o1 = v1;
}

__device__ __forceinline__ int fps_seed_index(int b) {
    uint32_t ka, kb, ra, rb;
    threefry2x32(0u, 42u, 0u, 1u, ka, kb);
    threefry2x32(ka, kb, 0u, (uint32_t)b, ra, rb);
    return (int)((ra ^ rb) & 4095u);
}

// ---------------- K1: farthest point sampling ----------------
__global__ void __launch_bounds__(256) fps_kernel(const float* __restrict__ pts) {
    __shared__ float rv[8];
    __shared__ int   ri[8];
    __shared__ float sc[3];
    __shared__ int   sFar;

    const int b = blockIdx.x;
    const int t = threadIdx.x;
    const float* P = pts + (size_t)b * 4096 * 3;

    float px[16], py[16], pz[16], dist[16];
#pragma unroll
    for (int k = 0; k < 16; k++) {
        int j = t + k * 256;
        px[k] = P[j * 3 + 0];
        py[k] = P[j * 3 + 1];
        pz[k] = P[j * 3 + 2];
        dist[k] = 1e10f;
    }
    if (t == 0) sFar = fps_seed_index(b);
    __syncthreads();

    {
        int far = sFar;
#pragma unroll
        for (int k = 0; k < 16; k++)
            if (t + k * 256 == far) { sc[0] = px[k]; sc[1] = py[k]; sc[2] = pz[k]; }
    }
    __syncthreads();

    for (int it = 0; it < 128; it++) {
        float cx = sc[0], cy = sc[1], cz = sc[2];
        if (t == 0) {
            float* o = g_newxyz + ((size_t)b * 128 + it) * 3;
            o[0] = cx; o[1] = cy; o[2] = cz;
        }
        float best = -1.0f;
        int bi = 0x7fffffff;
#pragma unroll
        for (int k = 0; k < 16; k++) {
            int j = t + k * 256;
            float dx = px[k] - cx, dy = py[k] - cy, dz = pz[k] - cz;
            float d = dx * dx + dy * dy + dz * dz;
            float nd = fminf(dist[k], d);
            dist[k] = nd;
            if (nd > best) { best = nd; bi = j; }
        }
#pragma unroll
        for (int off = 16; off; off >>= 1) {
            float ov = __shfl_down_sync(0xffffffffu, best, off);
            int   oi = __shfl_down_sync(0xffffffffu, bi, off);
            if (ov > best || (ov == best && oi < bi)) { best = ov; bi = oi; }
        }
        if ((t & 31) == 0) { rv[t >> 5] = best; ri[t >> 5] = bi; }
        __syncthreads();
        if (t < 32) {
            float v = (t < 8) ? rv[t] : -1e30f;
            int   ix = (t < 8) ? ri[t] : 0x7fffffff;
#pragma unroll
            for (int off = 4; off; off >>= 1) {
                float ov = __shfl_down_sync(0xffffffffu, v, off);
                int   oi = __shfl_down_sync(0xffffffffu, ix, off);
                if (ov > v || (ov == v && oi < ix)) { v = ov; ix = oi; }
            }
            if (t == 0) sFar = ix;
        }
        __syncthreads();
        {
            int far = sFar;
#pragma unroll
            for (int k = 0; k < 16; k++)
                if (t + k * 256 == far) { sc[0] = px[k]; sc[1] = py[k]; sc[2] = pz[k]; }
        }
        __syncthreads();
    }
}

// ---------------- smem tile loader: 128 rows x 32 floats ----------------
__device__ __forceinline__ void load_tile(const float* __restrict__ gptr, int ldg,
                                          float* sptr, int t) {
#pragma unroll
    for (int i = 0; i < 4; i++) {
        int idx = t + i * 256;          // float4 index 0..1023
        int row = idx >> 3, q = idx & 7;
        float4 v = *(const float4*)(gptr + (size_t)row * ldg + q * 4);
        *(float4*)(sptr + row * LDA + q * 4) = v;
    }
}

// ---------------- K2: fused stage-1 wmma tf32 GEMM + BN + ReLU ----------------
// grid (324, 4): blocks 0-97 rgb, 98-195 depth, 196-259 mmwave, 260-323 lidar
__global__ void __launch_bounds__(256) wmma_stage1_kernel(
    const float* __restrict__ rgb, const float* __restrict__ depth,
    const float* __restrict__ mmw, const float* __restrict__ lid,
    const float* __restrict__ conv_w, const float* __restrict__ cb4,
    const float* __restrict__ gg4, const float* __restrict__ bb4,
    const float* __restrict__ bm4, const float* __restrict__ bv4)
{
    __shared__ float As[128 * LDA];
    __shared__ float Bs[128 * LDA];
    __shared__ float s_alpha[128], s_beta[128];

    const int blk = blockIdx.x;
    int mod, rb, region;
    if (blk < 98)       { mod = 0; rb = blk;       region = 0; }
    else if (blk < 196) { mod = 1; rb = blk - 98;  region = 12544; }
    else if (blk < 260) { mod = 2; rb = blk - 196; region = 25088; }
    else                { mod = 3; rb = blk - 260; region = 33280; }
    const float* X  = (mod == 0) ? rgb : (mod == 1) ? depth : (mod == 2) ? mmw : lid;
    const float* W  = conv_w + (size_t)mod * 262144;
    const float* cb = cb4 + mod * 512;
    const float* gg = gg4 + mod * 512;
    const float* bb = bb4 + mod * 512;
    const float* bm = bm4 + mod * 512;
    const float* bv = bv4 + mod * 512;

    const int row0 = rb * 128;
    const int col0 = blockIdx.y * 128;
    const int t = threadIdx.x;

    if (t < 128) {
        int o = col0 + t;
        float al = gg[o] * rsqrtf(bv[o] + EPSV);
        s_alpha[t] = al;
        s_beta[t]  = (cb[o] - bm[o]) * al + bb[o];
    }

    const int wid = t >> 5, lane = t & 31;
    const int wm = wid & 3, wn = wid >> 2;

    wmma::fragment<wmma::accumulator, 16, 16, 8, float> c[2][4];
#pragma unroll
    for (int i = 0; i < 2; i++)
#pragma unroll
        for (int j = 0; j < 4; j++) wmma::fill_fragment(c[i][j], 0.0f);

    const float* Ab = X + (size_t)row0 * 512;
    const float* Bb = W + (size_t)col0 * 512;

    for (int kt = 0; kt < 16; kt++) {
        load_tile(Ab + kt * 32, 512, As, t);
        load_tile(Bb + kt * 32, 512, Bs, t);
        __syncthreads();
#pragma unroll
        for (int ks = 0; ks < 4; ks++) {
            const int k0 = ks * 8;
            wmma::fragment<wmma::matrix_a, 16, 16, 8, wmma::precision::tf32, wmma::row_major> a[2];
            wmma::fragment<wmma::matrix_b, 16, 16, 8, wmma::precision::tf32, wmma::col_major> b[4];
#pragma unroll
            for (int i = 0; i < 2; i++) {
                wmma::load_matrix_sync(a[i], As + (wm * 32 + i * 16) * LDA + k0, LDA);
#pragma unroll
                for (int e = 0; e < a[i].num_elements; e++)
                    a[i].x[e] = wmma::__float_to_tf32(a[i].x[e]);
            }
#pragma unroll
            for (int j = 0; j < 4; j++) {
                wmma::load_matrix_sync(b[j], Bs + (wn * 64 + j * 16) * LDA + k0, LDA);
#pragma unroll
                for (int e = 0; e < b[j].num_elements; e++)
                    b[j].x[e] = wmma::__float_to_tf32(b[j].x[e]);
            }
#pragma unroll
            for (int i = 0; i < 2; i++)
#pragma unroll
                for (int j = 0; j < 4; j++)
                    wmma::mma_sync(c[i][j], a[i], b[j], c[i][j]);
        }
        __syncthreads();
    }

    // epilogue: BN + ReLU through tiny per-warp staging tile
    float* stg = As + wid * (16 * LDS_STG);
    const int r = lane >> 1, cs = (lane & 1) * 8;
#pragma unroll
    for (int i = 0; i < 2; i++)
#pragma unroll
        for (int j = 0; j < 4; j++) {
            wmma::store_matrix_sync(stg, c[i][j], LDS_STG, wmma::mem_row_major);
            __syncwarp();
            const int gc = wn * 64 + j * 16 + cs;
            float ov[8];
#pragma unroll
            for (int q = 0; q < 8; q++) {
                float v = stg[r * LDS_STG + cs + q];
                ov[q] = fmaxf(fmaf(v, s_alpha[gc + q], s_beta[gc + q]), 0.0f);
            }
            float* hp = g_H + (size_t)(region + row0 + wm * 32 + i * 16 + r) * 512 + col0 + gc;
            *(float4*)hp       = make_float4(ov[0], ov[1], ov[2], ov[3]);
            *(float4*)(hp + 4) = make_float4(ov[4], ov[5], ov[6], ov[7]);
            __syncwarp();
        }
}

// ---------------- K3: token linear (L -> 32) + ReLU, writes proj into d_out ----------------
__global__ void __launch_bounds__(256) stage2_kernel(
    const float* __restrict__ lwimg, const float* __restrict__ lbimg,
    const float* __restrict__ lwpc,  const float* __restrict__ lbpc,
    float* __restrict__ out)
{
    const int b = blockIdx.x, m = blockIdx.y, t = threadIdx.x;
    const int L = (m < 2) ? 49 : 32;
    const int start = (m < 2) ? m * 12544 : 25088 + (m - 2) * 8192;
    const float* lw = (m == 0) ? lwimg
                    : (m == 1) ? lwimg + 32 * 49
                    : (m == 2) ? lwpc
                               : lwpc + 32 * 32;
    const float* lb = (m < 2) ? lbimg + m * 32 : lbpc + (m - 2) * 32;

    __shared__ float slw[32 * 49];
    for (int i = t; i < 32 * L; i += 256) slw[i] = lw[i];
    __syncthreads();

    const int o0 = (t & 63) * 8;
    const int s0 = (t >> 6) * 8;
    float acc[8][8];
#pragma unroll
    for (int i = 0; i < 8; i++)
#pragma unroll
        for (int j = 0; j < 8; j++) acc[i][j] = 0.0f;

    const float* hp = g_H + (size_t)(start + b * L) * 512 + o0;
    for (int l = 0; l < L; l++) {
        float4 h0 = *(const float4*)hp;
        float4 h1 = *(const float4*)(hp + 4);
        hp += 512;
        float hv[8] = {h0.x, h0.y, h0.z, h0.w, h1.x, h1.y, h1.z, h1.w};
#pragma unroll
        for (int i = 0; i < 8; i++) {
            float w = slw[(s0 + i) * L + l];
#pragma unroll
            for (int j = 0; j < 8; j++) acc[i][j] = fmaf(w, hv[j], acc[i][j]);
        }
    }
#pragma unroll
    for (int i = 0; i < 8; i++) {
        int s = s0 + i;
        float bias = lb[s];
        float ov[8];
#pragma unroll
        for (int j = 0; j < 8; j++) ov[j] = fmaxf(acc[i][j] + bias, 0.0f);
        float* op = out + ((size_t)b * 128 + m * 32 + s) * 512 + o0;
        *(float4*)op       = make_float4(ov[0], ov[1], ov[2], ov[3]);
        *(float4*)(op + 4) = make_float4(ov[4], ov[5], ov[6], ov[7]);
    }
}

// ---------------- K4a: posenc layer 1 (3 -> 128) + BN + ReLU ----------------
__global__ void __launch_bounds__(256) h1_kernel(
    const float* __restrict__ w1, const float* __restrict__ b1,
    const float* __restrict__ g1, const float* __restrict__ bb1,
    const float* __restrict__ m1, const float* __restrict__ v1)
{
    int idx = blockIdx.x * 256 + threadIdx.x;
    int row = idx >> 7;
    int c = idx & 127;
    const float* xyz = g_newxyz + (size_t)row * 3;
    float x = xyz[0], y = xyz[1], z = xyz[2];
    float v = w1[c * 3 + 0] * x + w1[c * 3 + 1] * y + w1[c * 3 + 2] * z + b1[c];
    float al = g1[c] * rsqrtf(v1[c] + EPSV);
    v = (v - m1[c]) * al + bb1[c];
    g_h1[(size_t)row * 128 + c] = fmaxf(v, 0.0f);
}

// ---------------- K4b: posenc layer-2 wmma tf32 GEMM + BN + ReLU, += out ----------------
__global__ void __launch_bounds__(256) wmma_posenc_kernel(
    const float* __restrict__ W,     // pe_w2 [512, 128], K contiguous
    const float* __restrict__ cb,
    const float* __restrict__ gg,
    const float* __restrict__ bbeta,
    const float* __restrict__ bmean,
    const float* __restrict__ bvar,
    float* __restrict__ out)
{
    __shared__ float As[128 * LDA];
    __shared__ float Bs[128 * LDA];
    __shared__ float s_alpha[128], s_beta[128];

    const int row0 = blockIdx.x * 128;
    const int col0 = blockIdx.y * 128;
    const int t = threadIdx.x;

    if (t < 128) {
        int o = col0 + t;
        float al = gg[o] * rsqrtf(bvar[o] + EPSV);
        s_alpha[t] = al;
        s_beta[t]  = (cb[o] - bmean[o]) * al + bbeta[o];
    }

    const int wid = t >> 5, lane = t & 31;
    const int wm = wid & 3, wn = wid >> 2;

    wmma::fragment<wmma::accumulator, 16, 16, 8, float> c[2][4];
#pragma unroll
    for (int i = 0; i < 2; i++)
#pragma unroll
        for (int j = 0; j < 4; j++) wmma::fill_fragment(c[i][j], 0.0f);

    const float* Ab = g_h1 + (size_t)row0 * 128;
    const float* Bb = W + (size_t)col0 * 128;

    for (int kt = 0; kt < 4; kt++) {
        load_tile(Ab + kt * 32, 128, As, t);
        load_tile(Bb + kt * 32, 128, Bs, t);
        __syncthreads();
#pragma unroll
        for (int ks = 0; ks < 4; ks++) {
            const int k0 = ks * 8;
            wmma::fragment<wmma::matrix_a, 16, 16, 8, wmma::precision::tf32, wmma::row_major> a[2];
            wmma::fragment<wmma::matrix_b, 16, 16, 8, wmma::precision::tf32, wmma::col_major> b[4];
#pragma unroll
            for (int i = 0; i < 2; i++) {
                wmma::load_matrix_sync(a[i], As + (wm * 32 + i * 16) * LDA + k0, LDA);
#pragma unroll
                for (int e = 0; e < a[i].num_elements; e++)
                    a[i].x[e] = wmma::__float_to_tf32(a[i].x[e]);
            }
#pragma unroll
            for (int j = 0; j < 4; j++) {
                wmma::load_matrix_sync(b[j], Bs + (wn * 64 + j * 16) * LDA + k0, LDA);
#pragma unroll
                for (int e = 0; e < b[j].num_elements; e++)
                    b[j].x[e] = wmma::__float_to_tf32(b[j].x[e]);
            }
#pragma unroll
            for (int i = 0; i < 2; i++)
#pragma unroll
                for (int j = 0; j < 4; j++)
                    wmma::mma_sync(c[i][j], a[i], b[j], c[i][j]);
        }
        __syncthreads();
    }

    float* stg = As + wid * (16 * LDS_STG);
    const int r = lane >> 1, cs = (lane & 1) * 8;
#pragma unroll
    for (int i = 0; i < 2; i++)
#pragma unroll
        for (int j = 0; j < 4; j++) {
            wmma::store_matrix_sync(stg, c[i][j], LDS_STG, wmma::mem_row_major);
            __syncwarp();
            const int gc = wn * 64 + j * 16 + cs;
            float* op = out + (size_t)(row0 + wm * 32 + i * 16 + r) * 512 + col0 + gc;
            float4 c0 = *(float4*)op;
            float4 c1 = *(float4*)(op + 4);
            float v0 = stg[r * LDS_STG + cs + 0];
            float v1 = stg[r * LDS_STG + cs + 1];
            float v2 = stg[r * LDS_STG + cs + 2];
            float v3 = stg[r * LDS_STG + cs + 3];
            float v4 = stg[r * LDS_STG + cs + 4];
            float v5 = stg[r * LDS_STG + cs + 5];
            float v6 = stg[r * LDS_STG + cs + 6];
            float v7 = stg[r * LDS_STG + cs + 7];
            c0.x += fmaxf(fmaf(v0, s_alpha[gc + 0], s_beta[gc + 0]), 0.0f);
            c0.y += fmaxf(fmaf(v1, s_alpha[gc + 1], s_beta[gc + 1]), 0.0f);
            c0.z += fmaxf(fmaf(v2, s_alpha[gc + 2], s_beta[gc + 2]), 0.0f);
            c0.w += fmaxf(fmaf(v3, s_alpha[gc + 3], s_beta[gc + 3]), 0.0f);
            c1.x += fmaxf(fmaf(v4, s_alpha[gc + 4], s_beta[gc + 4]), 0.0f);
            c1.y += fmaxf(fmaf(v5, s_alpha[gc + 5], s_beta[gc + 5]), 0.0f);
            c1.z += fmaxf(fmaf(v6, s_alpha[gc + 6], s_beta[gc + 6]), 0.0f);
            c1.w += fmaxf(fmaf(v7, s_alpha[gc + 7], s_beta[gc + 7]), 0.0f);
            *(float4*)op       = c0;
            *(float4*)(op + 4) = c1;
            __syncwarp();
        }
}

// ---------------- launch ----------------
extern "C" void kernel_launch(void* const* d_in, const int* in_sizes, int n_in,
                              void* d_out, int out_size) {
    const float* rgb     = (const float*)d_in[0];
    const float* depth   = (const float*)d_in[1];
    const float* mmwave  = (const float*)d_in[2];
    const float* lidar   = (const float*)d_in[3];
    const float* pts     = (const float*)d_in[4];
    const float* conv_w  = (const float*)d_in[5];
    const float* conv_b  = (const float*)d_in[6];
    const float* bn_g    = (const float*)d_in[7];
    const float* bn_b    = (const float*)d_in[8];
    const float* bn_m    = (const float*)d_in[9];
    const float* bn_v    = (const float*)d_in[10];
    const float* lwimg   = (const float*)d_in[11];
    const float* lbimg   = (const float*)d_in[12];
    const float* lwpc    = (const float*)d_in[13];
    const float* lbpc    = (const float*)d_in[14];
    const float* pw1     = (const float*)d_in[15];
    const float* pb1     = (const float*)d_in[16];
    const float* pg1     = (const float*)d_in[17];
    const float* pbb1    = (const float*)d_in[18];
    const float* pm1     = (const float*)d_in[19];
    const float* pv1     = (const float*)d_in[20];
    const float* pw2     = (const float*)d_in[21];
    const float* pb2     = (const float*)d_in[22];
    const float* pg2     = (const float*)d_in[23];
    const float* pbb2    = (const float*)d_in[24];
    const float* pm2     = (const float*)d_in[25];
    const float* pv2     = (const float*)d_in[26];
    float* out = (float*)d_out;

    // FPS (independent of GEMMs)
    fps_kernel<<<256, 256>>>(pts);

    // stage-1: all 4 modalities in one fused tf32 wmma launch
    wmma_stage1_kernel<<<dim3(324, 4), 256>>>(rgb, depth, mmwave, lidar,
                                              conv_w, conv_b, bn_g, bn_b, bn_m, bn_v);

    // stage-2: proj written to d_out
    stage2_kernel<<<dim3(256, 4), 256>>>(lwimg, lbimg, lwpc, lbpc, out);

    // posenc layer 1 (elementwise) then layer-2 tf32 GEMM accumulated into d_out
    h1_kernel<<<16384, 256>>>(pw1, pb1, pg1, pbb1, pm1, pv1);
    wmma_posenc_kernel<<<dim3(256, 4), 256>>>(pw2, pb2, pg2, pbb2, pm2, pv2, out);
}